// round 6
// baseline (speedup 1.0000x reference)
#include <cuda_runtime.h>
#include <math.h>
#include <stdint.h>

#define S_LEN    4096
#define D_MODEL  1024
#define NUM_HEADS 16
#define HEAD_DIM  64

// Scratch (allocation-free rule: __device__ globals).
// g_q/g_k: [h][s][d'] tf32 bits, d' = paired order within 8-chunks.
// g_vt:    [h][d][s'] tf32 bits, transposed, s' paired within 8-chunks.
__device__ uint32_t g_q [NUM_HEADS * S_LEN * HEAD_DIM];
__device__ uint32_t g_k [NUM_HEADS * S_LEN * HEAD_DIM];
__device__ uint32_t g_vt[NUM_HEADS * HEAD_DIM * S_LEN];
__device__ float    g_attn[S_LEN * D_MODEL];            // [s][h*64+d]

// ---------------------------------------------------------------------------
// helpers
// ---------------------------------------------------------------------------
__device__ __forceinline__ uint32_t f2tf32(float f) {
    uint32_t u;
    asm("cvt.rna.tf32.f32 %0, %1;" : "=r"(u) : "f"(f));
    return u;
}

__device__ __forceinline__ void mma_tf32(float c[4],
                                         uint32_t a0, uint32_t a1, uint32_t a2, uint32_t a3,
                                         uint32_t b0, uint32_t b1) {
    asm volatile(
        "mma.sync.aligned.m16n8k8.row.col.f32.tf32.tf32.f32 "
        "{%0,%1,%2,%3}, {%4,%5,%6,%7}, {%8,%9}, {%0,%1,%2,%3};"
        : "+f"(c[0]), "+f"(c[1]), "+f"(c[2]), "+f"(c[3])
        : "r"(a0), "r"(a1), "r"(a2), "r"(a3), "r"(b0), "r"(b1));
}

// paired position within an 8-chunk: 0,4,1,5,2,6,3,7 -> (x, x+4) adjacent
__device__ __forceinline__ int dpair(int d) {
    return (d & ~7) | ((d & 3) << 1) | ((d & 4) >> 2);
}

__device__ __forceinline__ void cpasync16(uint32_t dst, const void* src) {
    asm volatile("cp.async.cg.shared.global [%0], [%1], 16;" :: "r"(dst), "l"(src));
}
#define CP_COMMIT() asm volatile("cp.async.commit_group;")
#define CP_WAIT0()  asm volatile("cp.async.wait_group 0;")

// ---------------------------------------------------------------------------
// tf32 GEMM (proven core): C[m,n] = sum_k A[m,k]*B[n,k]
// MODE 0: qkv epilogue -> tf32-bit scatter into g_q (x0.125) / g_k / g_vt.
// MODE 1: plain fp32 store.
// ---------------------------------------------------------------------------
#define PITCH 20

template <int MODE>
__global__ __launch_bounds__(256) void gemm_tf32_kernel(const float* __restrict__ A,
                                                        const float* __restrict__ B,
                                                        float* __restrict__ C,
                                                        int ldk) {
    __shared__ uint32_t As[2][128 * PITCH];
    __shared__ uint32_t Bs[2][128 * PITCH];

    const int m0 = blockIdx.x * 128;
    const int n0 = blockIdx.y * 128;
    const int t = threadIdx.x;
    const int warp = t >> 5, lane = t & 31;
    const int warpM = warp >> 2, warpN = warp & 3;
    const int g = lane >> 2, th = lane & 3;

    const float* Ag = A + (size_t)m0 * ldk;
    const float* Bg = B + (size_t)n0 * ldk;

    const int lm0 = t >> 2, lkv = (t & 3) * 4;
    const int lm1 = (t + 256) >> 2;

    float acc[4][4][4];
#pragma unroll
    for (int mt = 0; mt < 4; mt++)
#pragma unroll
        for (int nt = 0; nt < 4; nt++)
#pragma unroll
            for (int i = 0; i < 4; i++) acc[mt][nt][i] = 0.0f;

    {
        float4 a0 = *(const float4*)&Ag[(size_t)lm0 * ldk + lkv];
        float4 a1 = *(const float4*)&Ag[(size_t)lm1 * ldk + lkv];
        float4 b0 = *(const float4*)&Bg[(size_t)lm0 * ldk + lkv];
        float4 b1 = *(const float4*)&Bg[(size_t)lm1 * ldk + lkv];
        *(uint4*)&As[0][lm0 * PITCH + lkv] = make_uint4(f2tf32(a0.x), f2tf32(a0.y), f2tf32(a0.z), f2tf32(a0.w));
        *(uint4*)&As[0][lm1 * PITCH + lkv] = make_uint4(f2tf32(a1.x), f2tf32(a1.y), f2tf32(a1.z), f2tf32(a1.w));
        *(uint4*)&Bs[0][lm0 * PITCH + lkv] = make_uint4(f2tf32(b0.x), f2tf32(b0.y), f2tf32(b0.z), f2tf32(b0.w));
        *(uint4*)&Bs[0][lm1 * PITCH + lkv] = make_uint4(f2tf32(b1.x), f2tf32(b1.y), f2tf32(b1.z), f2tf32(b1.w));
    }
    __syncthreads();

    const int NITER = D_MODEL / 16;
    int buf = 0;

    for (int it = 0; it < NITER; it++) {
        float4 ra0, ra1, rb0, rb1;
        if (it < NITER - 1) {
            int k0 = (it + 1) * 16;
            ra0 = *(const float4*)&Ag[(size_t)lm0 * ldk + k0 + lkv];
            ra1 = *(const float4*)&Ag[(size_t)lm1 * ldk + k0 + lkv];
            rb0 = *(const float4*)&Bg[(size_t)lm0 * ldk + k0 + lkv];
            rb1 = *(const float4*)&Bg[(size_t)lm1 * ldk + k0 + lkv];
        }

#pragma unroll
        for (int ks = 0; ks < 2; ks++) {
            uint32_t af[4][4], bf[4][2];
#pragma unroll
            for (int mt = 0; mt < 4; mt++) {
                int r = warpM * 64 + mt * 16 + g;
                af[mt][0] = As[buf][r * PITCH + ks * 8 + th];
                af[mt][1] = As[buf][(r + 8) * PITCH + ks * 8 + th];
                af[mt][2] = As[buf][r * PITCH + ks * 8 + th + 4];
                af[mt][3] = As[buf][(r + 8) * PITCH + ks * 8 + th + 4];
            }
#pragma unroll
            for (int nt = 0; nt < 4; nt++) {
                int c = warpN * 32 + nt * 8 + g;
                bf[nt][0] = Bs[buf][c * PITCH + ks * 8 + th];
                bf[nt][1] = Bs[buf][c * PITCH + ks * 8 + th + 4];
            }
#pragma unroll
            for (int mt = 0; mt < 4; mt++)
#pragma unroll
                for (int nt = 0; nt < 4; nt++)
                    mma_tf32(acc[mt][nt], af[mt][0], af[mt][1], af[mt][2], af[mt][3],
                             bf[nt][0], bf[nt][1]);
        }

        if (it < NITER - 1) {
            int nb = buf ^ 1;
            *(uint4*)&As[nb][lm0 * PITCH + lkv] = make_uint4(f2tf32(ra0.x), f2tf32(ra0.y), f2tf32(ra0.z), f2tf32(ra0.w));
            *(uint4*)&As[nb][lm1 * PITCH + lkv] = make_uint4(f2tf32(ra1.x), f2tf32(ra1.y), f2tf32(ra1.z), f2tf32(ra1.w));
            *(uint4*)&Bs[nb][lm0 * PITCH + lkv] = make_uint4(f2tf32(rb0.x), f2tf32(rb0.y), f2tf32(rb0.z), f2tf32(rb0.w));
            *(uint4*)&Bs[nb][lm1 * PITCH + lkv] = make_uint4(f2tf32(rb1.x), f2tf32(rb1.y), f2tf32(rb1.z), f2tf32(rb1.w));
            __syncthreads();
            buf = nb;
        }
    }

#pragma unroll
    for (int mt = 0; mt < 4; mt++) {
#pragma unroll
        for (int nt = 0; nt < 4; nt++) {
            int row = m0 + warpM * 64 + mt * 16 + g;
            int col = n0 + warpN * 32 + nt * 8 + 2 * th;
            if (MODE == 0) {
                int which = col >> 10;
                int h  = (col >> 6) & (NUM_HEADS - 1);
                int dd = col & (HEAD_DIM - 1);
                float s = (which == 0) ? 0.125f : 1.0f;
                uint32_t v0 = f2tf32(acc[mt][nt][0] * s);
                uint32_t v1 = f2tf32(acc[mt][nt][1] * s);
                uint32_t v2 = f2tf32(acc[mt][nt][2] * s);
                uint32_t v3 = f2tf32(acc[mt][nt][3] * s);
                if (which == 2) {
                    // g_vt[h][dd][s'] transposed, s paired
                    uint32_t* b0 = g_vt + ((size_t)(h * HEAD_DIM + dd)) * S_LEN;
                    uint32_t* b1 = b0 + S_LEN;   // dd+1
                    int ps0 = dpair(row), ps1 = dpair(row + 8);
                    b0[ps0] = v0;  b1[ps0] = v1;
                    b0[ps1] = v2;  b1[ps1] = v3;
                } else {
                    uint32_t* dst = (which == 0 ? g_q : g_k) + ((size_t)h * S_LEN + row) * HEAD_DIM;
                    int p0 = dpair(dd), p1 = dpair(dd + 1);
                    dst[p0] = v0;           dst[p1] = v1;
                    dst[8 * HEAD_DIM + p0] = v2;  dst[8 * HEAD_DIM + p1] = v3;
                }
            } else {
                *(float2*)&C[(size_t)row * D_MODEL + col] =
                    make_float2(acc[mt][nt][0], acc[mt][nt][1]);
                *(float2*)&C[(size_t)(row + 8) * D_MODEL + col] =
                    make_float2(acc[mt][nt][2], acc[mt][nt][3]);
            }
        }
    }
}

// ---------------------------------------------------------------------------
// Flash attention, tf32 mma, cp.async double-buffered K/V.
// 128 thr / 4 warps, BQ=64 (16 rows/warp), BKV=64.
// Smem: 2 x (K 16KB + V 16KB) = 64 KB; pitch 64 words, chunk-XOR swizzle
// (chunk ^= row&15). All fragment loads are LDS.64 via paired layouts.
// P reuses the current K buffer after S-phase (one syncthreads).
// ---------------------------------------------------------------------------
#define KVW 4096                       // words per 64x64 tile
#define FA_SMEM_BYTES (4 * KVW * 4)    // 64 KB

__global__ __launch_bounds__(128, 3) void flash_attn_mma_kernel() {
    extern __shared__ uint32_t sm[];

    const int qb = (int)gridDim.x - 1 - (int)blockIdx.x;  // longest first
    const int h  = blockIdx.y;
    const int t = threadIdx.x, warp = t >> 5, lane = t & 31;
    const int g = lane >> 2, th = lane & 3;
    const int thu = th >> 1, thw = 2 * (th & 1);
    const int row0 = qb * 64 + warp * 16 + g;   // second row = row0 + 8

    const uint32_t* KgH = g_k  + (size_t)h * S_LEN * HEAD_DIM;
    const uint32_t* VgH = g_vt + (size_t)h * HEAD_DIM * S_LEN;

    const uint32_t sbase = (uint32_t)__cvta_generic_to_shared(sm);

    // ---- prefetch tile 0 into buffer 0 ----
    {
#pragma unroll
        for (int i = 0; i < 8; i++) {
            int id = t + (i << 7);               // 0..1023
            int r = id >> 4, ch = id & 15;
            int dch = ch ^ (r & 15);
            uint32_t doff = (uint32_t)(r * 64 + dch * 4) * 4;
            cpasync16(sbase + doff,        KgH + (size_t)r * HEAD_DIM + ch * 4);
            cpasync16(sbase + 16384 + doff, VgH + (size_t)r * S_LEN + ch * 4);
        }
        CP_COMMIT();
    }

    // ---- Q fragments (pre-scaled, pre-converted, paired): 16 LDG.64 ----
    uint32_t qf[8][4];
    {
        const uint32_t* Qg0 = g_q + ((size_t)h * S_LEN + row0) * HEAD_DIM;
        const uint32_t* Qg1 = Qg0 + 8 * HEAD_DIM;
#pragma unroll
        for (int kc = 0; kc < 8; kc++) {
            uint2 qa = *(const uint2*)(Qg0 + kc * 8 + 2 * th);   // (a0, a2)
            uint2 qb2 = *(const uint2*)(Qg1 + kc * 8 + 2 * th);  // (a1, a3)
            qf[kc][0] = qa.x;  qf[kc][1] = qb2.x;
            qf[kc][2] = qa.y;  qf[kc][3] = qb2.y;
        }
    }

    float acc[8][4];
#pragma unroll
    for (int n = 0; n < 8; n++)
#pragma unroll
        for (int i = 0; i < 4; i++) acc[n][i] = 0.0f;
    float m0 = -1e30f, m1 = -1e30f, l0 = 0.0f, l1 = 0.0f;

    const int pr0 = warp * 16 + g, pr1 = pr0 + 8;   // P rows in current K buf
    const int pp0 = (th < 2) ? 4 * th : 4 * th - 7; // pos(2*th) within 8-chunk

    for (int kb = 0; kb <= qb; kb++) {
        const int b = kb & 1;
        uint32_t* Kt = sm + b * (2 * KVW);
        uint32_t* Vt = Kt + KVW;

        CP_WAIT0();
        __syncthreads();     // tile visible to all; prev-iter buffers free

        if (kb < qb) {       // prefetch next tile into other buffer
            int nb = b ^ 1;
            uint32_t kd = sbase + nb * 32768;
            const uint32_t* Kn = KgH + (size_t)(kb + 1) * 64 * HEAD_DIM;
            const uint32_t* Vn = VgH + (kb + 1) * 64;
#pragma unroll
            for (int i = 0; i < 8; i++) {
                int id = t + (i << 7);
                int r = id >> 4, ch = id & 15;
                int dch = ch ^ (r & 15);
                uint32_t doff = (uint32_t)(r * 64 + dch * 4) * 4;
                cpasync16(kd + doff,         Kn + (size_t)r * HEAD_DIM + ch * 4);
                cpasync16(kd + 16384 + doff, Vn + (size_t)r * S_LEN + ch * 4);
            }
            CP_COMMIT();
        }

        // ---- S = Q @ K^T : LDS.64 b-pairs ----
        float sc[8][4];
#pragma unroll
        for (int n = 0; n < 8; n++)
#pragma unroll
            for (int i = 0; i < 4; i++) sc[n][i] = 0.0f;

#pragma unroll
        for (int kc = 0; kc < 8; kc++) {
            const int cb = 2 * kc + thu;
#pragma unroll
            for (int nt = 0; nt < 8; nt++) {
                int r = nt * 8 + g;
                uint2 bb = *(const uint2*)(Kt + r * 64 + ((cb ^ (r & 15)) << 2) + thw);
                mma_tf32(sc[nt], qf[kc][0], qf[kc][1], qf[kc][2], qf[kc][3], bb.x, bb.y);
            }
        }

        // ---- causal mask (diagonal tile only) ----
        if (kb == qb) {
#pragma unroll
            for (int nt = 0; nt < 8; nt++) {
                int c0 = kb * 64 + nt * 8 + 2 * th;
                if (c0 > row0)         sc[nt][0] = -1e30f;
                if (c0 + 1 > row0)     sc[nt][1] = -1e30f;
                if (c0 > row0 + 8)     sc[nt][2] = -1e30f;
                if (c0 + 1 > row0 + 8) sc[nt][3] = -1e30f;
            }
        }

        // ---- online softmax ----
        float tm0 = -1e30f, tm1 = -1e30f;
#pragma unroll
        for (int nt = 0; nt < 8; nt++) {
            tm0 = fmaxf(tm0, fmaxf(sc[nt][0], sc[nt][1]));
            tm1 = fmaxf(tm1, fmaxf(sc[nt][2], sc[nt][3]));
        }
        tm0 = fmaxf(tm0, __shfl_xor_sync(0xffffffffu, tm0, 1));
        tm0 = fmaxf(tm0, __shfl_xor_sync(0xffffffffu, tm0, 2));
        tm1 = fmaxf(tm1, __shfl_xor_sync(0xffffffffu, tm1, 1));
        tm1 = fmaxf(tm1, __shfl_xor_sync(0xffffffffu, tm1, 2));

        float mn0 = fmaxf(m0, tm0), mn1 = fmaxf(m1, tm1);
        float corr0 = __expf(m0 - mn0), corr1 = __expf(m1 - mn1);

        float ps0 = 0.0f, ps1 = 0.0f;
#pragma unroll
        for (int nt = 0; nt < 8; nt++) {
            sc[nt][0] = __expf(sc[nt][0] - mn0);
            sc[nt][1] = __expf(sc[nt][1] - mn0);
            sc[nt][2] = __expf(sc[nt][2] - mn1);
            sc[nt][3] = __expf(sc[nt][3] - mn1);
            ps0 += sc[nt][0] + sc[nt][1];
            ps1 += sc[nt][2] + sc[nt][3];
        }
        ps0 += __shfl_xor_sync(0xffffffffu, ps0, 1);
        ps0 += __shfl_xor_sync(0xffffffffu, ps0, 2);
        ps1 += __shfl_xor_sync(0xffffffffu, ps1, 1);
        ps1 += __shfl_xor_sync(0xffffffffu, ps1, 2);

        l0 = l0 * corr0 + ps0;  m0 = mn0;
        l1 = l1 * corr1 + ps1;  m1 = mn1;
#pragma unroll
        for (int nt = 0; nt < 8; nt++) {
            acc[nt][0] *= corr0;  acc[nt][1] *= corr0;
            acc[nt][2] *= corr1;  acc[nt][3] *= corr1;
        }

        __syncthreads();   // all warps finished reading K -> reuse as P

        // ---- P -> K buffer (paired cols + chunk swizzle) ----
#pragma unroll
        for (int nt = 0; nt < 8; nt++) {
            int w0 = nt * 8 + pp0;      // pos(2th)
            int w1 = w0 + 2;            // pos(2th+1)
            Kt[pr0 * 64 + (((w0 >> 2) ^ (pr0 & 15)) << 2) + (w0 & 3)] = f2tf32(sc[nt][0]);
            Kt[pr0 * 64 + (((w1 >> 2) ^ (pr0 & 15)) << 2) + (w1 & 3)] = f2tf32(sc[nt][1]);
            Kt[pr1 * 64 + (((w0 >> 2) ^ (pr1 & 15)) << 2) + (w0 & 3)] = f2tf32(sc[nt][2]);
            Kt[pr1 * 64 + (((w1 >> 2) ^ (pr1 & 15)) << 2) + (w1 & 3)] = f2tf32(sc[nt][3]);
        }
        __syncwarp();

        // ---- acc += P @ V : LDS.64 a-pairs + b-pairs ----
#pragma unroll
        for (int kc = 0; kc < 8; kc++) {
            const int cb = 2 * kc + thu;
            uint2 pa = *(const uint2*)(Kt + pr0 * 64 + ((cb ^ (pr0 & 15)) << 2) + thw); // (a0,a2)
            uint2 pb = *(const uint2*)(Kt + pr1 * 64 + ((cb ^ (pr1 & 15)) << 2) + thw); // (a1,a3)
#pragma unroll
            for (int nt2 = 0; nt2 < 8; nt2++) {
                int rv = nt2 * 8 + g;
                uint2 vv = *(const uint2*)(Vt + rv * 64 + ((cb ^ (rv & 15)) << 2) + thw);
                mma_tf32(acc[nt2], pa.x, pb.x, pa.y, pb.y, vv.x, vv.y);
            }
        }
    }

    // ---- epilogue: normalize, write [s][h*64+d] ----
    float inv0 = 1.0f / l0, inv1 = 1.0f / l1;
#pragma unroll
    for (int nt2 = 0; nt2 < 8; nt2++) {
        int col = h * HEAD_DIM + nt2 * 8 + 2 * th;
        *(float2*)&g_attn[(size_t)row0 * D_MODEL + col] =
            make_float2(acc[nt2][0] * inv0, acc[nt2][1] * inv0);
        *(float2*)&g_attn[(size_t)(row0 + 8) * D_MODEL + col] =
            make_float2(acc[nt2][2] * inv1, acc[nt2][3] * inv1);
    }
}

// ---------------------------------------------------------------------------
extern "C" void kernel_launch(void* const* d_in, const int* in_sizes, int n_in,
                              void* d_out, int out_size) {
    const float* x     = (const float*)d_in[0];
    const float* w_qkv = (const float*)d_in[1];
    const float* w_out = (const float*)d_in[2];
    float* y = (float*)d_out;

    gemm_tf32_kernel<0><<<dim3(S_LEN / 128, (3 * D_MODEL) / 128), 256>>>(x, w_qkv, nullptr, D_MODEL);

    cudaFuncSetAttribute(flash_attn_mma_kernel,
                         cudaFuncAttributeMaxDynamicSharedMemorySize, FA_SMEM_BYTES);
    flash_attn_mma_kernel<<<dim3(S_LEN / 64, NUM_HEADS), 128, FA_SMEM_BYTES>>>();

    float* attn_ptr;
    cudaGetSymbolAddress((void**)&attn_ptr, g_attn);
    gemm_tf32_kernel<1><<<dim3(S_LEN / 128, D_MODEL / 128), 256>>>(attn_ptr, w_out, y, D_MODEL);
}